// round 3
// baseline (speedup 1.0000x reference)
#include <cuda_runtime.h>
#include <cuda_fp16.h>
#include <cstdint>

#define NMAX 100000
#define NHALF 50000              // node range per agg2 pass
#define HWORDS ((NMAX + 1) / 2)  // packed uint16x2 degree words

// Scratch (device globals: no allocation allowed)
__device__ uint32_t g_degpack[HWORDS];
__device__ float    g_dinv[NMAX];
__device__ __half   g_p[NMAX];     // 200 KB -> L1-resident gather array
__device__ float    g_t[NMAX];
__device__ __half2  g_rh[NMAX];    // 400 KB; gathered in 200 KB halves
__device__ float2   g_acc[NMAX];

__device__ __forceinline__ void red_add_u32(uint32_t* addr, uint32_t v) {
    asm volatile("red.global.add.u32 [%0], %1;" :: "l"(addr), "r"(v) : "memory");
}
__device__ __forceinline__ void red_add_f32(float* addr, float v) {
    asm volatile("red.global.add.f32 [%0], %1;" :: "l"(addr), "f"(v) : "memory");
}
__device__ __forceinline__ void red_add_v2(float2* addr, float x, float y) {
    asm volatile("red.global.add.v2.f32 [%0], {%1, %2};"
                 :: "l"(addr), "f"(x), "f"(y) : "memory");
}

// ---------------- node kernels ----------------

__global__ void k_init() {
    int i = blockIdx.x * blockDim.x + threadIdx.x;
    if (i < HWORDS) g_degpack[i] = 0u;
}

__global__ void k_node1(const float* __restrict__ x, int n) {
    int i = blockIdx.x * blockDim.x + threadIdx.x;
    if (i < n) {
        uint32_t pack = g_degpack[i >> 1];
        uint32_t cnt = (pack >> ((i & 1) * 16)) & 0xFFFFu;
        float d = rsqrtf(1.0f + (float)cnt);   // +1 = self-loop
        g_dinv[i] = d;
        float p = d * x[i];
        g_p[i] = __float2half(p);
        g_t[i] = p;  // self-loop term of layer-1 aggregation (full precision)
    }
}

__global__ void k_node2(const float* __restrict__ W1, const float* __restrict__ b1,
                        const float* __restrict__ W2, int n) {
    int i = blockIdx.x * blockDim.x + threadIdx.x;
    if (i < n) {
        float dv = g_dinv[i];
        float s = dv * g_t[i];  // layer-1 aggregated scalar
        float g0 = 0.0f, g1 = 0.0f;
        #pragma unroll
        for (int j = 0; j < 16; j++) {
            float h = fmaxf(fmaf(s, __ldg(&W1[j]), __ldg(&b1[j])), 0.0f);
            g0 = fmaf(h, __ldg(&W2[2 * j + 0]), g0);
            g1 = fmaf(h, __ldg(&W2[2 * j + 1]), g1);
        }
        float2 r = make_float2(dv * g0, dv * g1);
        g_rh[i] = __float22half2_rn(r);  // half for L1-resident gathers
        g_acc[i] = r;                    // self-loop term stays fp32
    }
}

__global__ void k_out(const float* __restrict__ b2, float* __restrict__ out, int n) {
    int i = blockIdx.x * blockDim.x + threadIdx.x;
    if (i < n) {
        float dv = g_dinv[i];
        float2 a = g_acc[i];
        float z0 = fmaf(dv, a.x, __ldg(&b2[0]));
        float z1 = fmaf(dv, a.y, __ldg(&b2[1]));
        float m = fmaxf(z0, z1);
        float lse = m + logf(expf(z0 - m) + expf(z1 - m));
        out[2 * i + 0] = z0 - lse;
        out[2 * i + 1] = z1 - lse;
    }
}

// ---------------- degree: direct packed 16-bit REDs ----------------

__global__ void k_deg(const int* __restrict__ dst, int E) {
    int i = blockIdx.x * blockDim.x + threadIdx.x;
    int base = i * 8;
    if (base + 7 < E) {
        int4 a = __ldcg(reinterpret_cast<const int4*>(dst) + 2 * i);
        int4 b = __ldcg(reinterpret_cast<const int4*>(dst) + 2 * i + 1);
        red_add_u32(&g_degpack[a.x >> 1], 1u << ((a.x & 1) * 16));
        red_add_u32(&g_degpack[a.y >> 1], 1u << ((a.y & 1) * 16));
        red_add_u32(&g_degpack[a.z >> 1], 1u << ((a.z & 1) * 16));
        red_add_u32(&g_degpack[a.w >> 1], 1u << ((a.w & 1) * 16));
        red_add_u32(&g_degpack[b.x >> 1], 1u << ((b.x & 1) * 16));
        red_add_u32(&g_degpack[b.y >> 1], 1u << ((b.y & 1) * 16));
        red_add_u32(&g_degpack[b.z >> 1], 1u << ((b.z & 1) * 16));
        red_add_u32(&g_degpack[b.w >> 1], 1u << ((b.w & 1) * 16));
    } else if (base < E) {
        for (int e = base; e < E; ++e) {
            int d = dst[e];
            red_add_u32(&g_degpack[d >> 1], 1u << ((d & 1) * 16));
        }
    }
}

// ---------------- layer-1 aggregation: single pass, L1-resident half p ------

__global__ void k_agg1(const int* __restrict__ src, const int* __restrict__ dst, int E) {
    int i = blockIdx.x * blockDim.x + threadIdx.x;
    int base = i * 8;
    if (base + 7 < E) {
        int4 sa = __ldcg(reinterpret_cast<const int4*>(src) + 2 * i);
        int4 sb = __ldcg(reinterpret_cast<const int4*>(src) + 2 * i + 1);
        int4 da = __ldcg(reinterpret_cast<const int4*>(dst) + 2 * i);
        int4 db = __ldcg(reinterpret_cast<const int4*>(dst) + 2 * i + 1);
        red_add_f32(&g_t[da.x], __half2float(__ldg(&g_p[sa.x])));
        red_add_f32(&g_t[da.y], __half2float(__ldg(&g_p[sa.y])));
        red_add_f32(&g_t[da.z], __half2float(__ldg(&g_p[sa.z])));
        red_add_f32(&g_t[da.w], __half2float(__ldg(&g_p[sa.w])));
        red_add_f32(&g_t[db.x], __half2float(__ldg(&g_p[sb.x])));
        red_add_f32(&g_t[db.y], __half2float(__ldg(&g_p[sb.y])));
        red_add_f32(&g_t[db.z], __half2float(__ldg(&g_p[sb.z])));
        red_add_f32(&g_t[db.w], __half2float(__ldg(&g_p[sb.w])));
    } else if (base < E) {
        for (int e = base; e < E; ++e)
            red_add_f32(&g_t[dst[e]], __half2float(__ldg(&g_p[src[e]])));
    }
}

// ---------------- layer-2 aggregation: 2 src-range passes, L1 half2 r ------

__global__ void k_agg2(const int* __restrict__ src, const int* __restrict__ dst,
                       int E, int lo, int hi) {
    int i = blockIdx.x * blockDim.x + threadIdx.x;
    int base = i * 8;
    if (base + 7 < E) {
        int4 sa = __ldcg(reinterpret_cast<const int4*>(src) + 2 * i);
        int4 sb = __ldcg(reinterpret_cast<const int4*>(src) + 2 * i + 1);
        int4 da = __ldcg(reinterpret_cast<const int4*>(dst) + 2 * i);
        int4 db = __ldcg(reinterpret_cast<const int4*>(dst) + 2 * i + 1);
        int s[8] = {sa.x, sa.y, sa.z, sa.w, sb.x, sb.y, sb.z, sb.w};
        int d[8] = {da.x, da.y, da.z, da.w, db.x, db.y, db.z, db.w};
        #pragma unroll
        for (int j = 0; j < 8; j++) {
            if (s[j] >= lo && s[j] < hi) {
                float2 r = __half22float2(__ldg(&g_rh[s[j]]));
                red_add_v2(&g_acc[d[j]], r.x, r.y);
            }
        }
    } else if (base < E) {
        for (int e = base; e < E; ++e) {
            int sv = src[e];
            if (sv >= lo && sv < hi) {
                float2 r = __half22float2(__ldg(&g_rh[sv]));
                red_add_v2(&g_acc[dst[e]], r.x, r.y);
            }
        }
    }
}

// ---------------- launch ----------------

extern "C" void kernel_launch(void* const* d_in, const int* in_sizes, int n_in,
                              void* d_out, int out_size) {
    const float* x  = (const float*)d_in[0];
    const int*   ei = (const int*)  d_in[1];
    const float* W1 = (const float*)d_in[2];
    const float* b1 = (const float*)d_in[3];
    const float* W2 = (const float*)d_in[4];
    const float* b2 = (const float*)d_in[5];
    int n = in_sizes[0];        // x is [N, 1]
    int E = in_sizes[1] / 2;    // edge_index is [2, E]
    const int* src = ei;
    const int* dst = ei + E;

    const int TB = 256;
    int nb_n = (n + TB - 1) / TB;
    int nb_h = (HWORDS + TB - 1) / TB;
    int e8   = (E + 7) / 8;
    int nb_e = (e8 + TB - 1) / TB;

    k_init <<<nb_h, TB>>>();
    k_deg  <<<nb_e, TB>>>(dst, E);
    k_node1<<<nb_n, TB>>>(x, n);
    k_agg1 <<<nb_e, TB>>>(src, dst, E);
    k_node2<<<nb_n, TB>>>(W1, b1, W2, n);
    k_agg2 <<<nb_e, TB>>>(src, dst, E, 0, NHALF);
    k_agg2 <<<nb_e, TB>>>(src, dst, E, NHALF, NMAX);
    k_out  <<<nb_n, TB>>>(b2, (float*)d_out, n);
}

// round 4
// speedup vs baseline: 1.2023x; 1.2023x over previous
#include <cuda_runtime.h>
#include <cuda_fp16.h>
#include <cstdint>

#define NMAX 100000
#define HWORDS ((NMAX + 1) / 2)  // packed uint16x2 degree words

// Scratch (device globals: no allocation allowed)
__device__ uint32_t g_degpack[HWORDS];
__device__ float    g_dinv[NMAX];
__device__ __half   g_p[NMAX];     // 200 KB gather array (layer 1)
__device__ float    g_t[NMAX];
__device__ __half2  g_rh[NMAX];    // 400 KB gather array (layer 2)
__device__ float2   g_acc[NMAX];

__device__ __forceinline__ void red_add_f32(float* addr, float v) {
    asm volatile("red.global.add.f32 [%0], %1;" :: "l"(addr), "f"(v) : "memory");
}
__device__ __forceinline__ void red_add_v2(float2* addr, float x, float y) {
    asm volatile("red.global.add.v2.f32 [%0], {%1, %2};"
                 :: "l"(addr), "f"(x), "f"(y) : "memory");
}

// ---------------- node kernels ----------------

__global__ void k_init() {
    int i = blockIdx.x * blockDim.x + threadIdx.x;
    if (i < HWORDS) g_degpack[i] = 0u;
}

__global__ void k_node1(const float* __restrict__ x, int n) {
    int i = blockIdx.x * blockDim.x + threadIdx.x;
    if (i < n) {
        uint32_t pack = g_degpack[i >> 1];
        uint32_t cnt = (pack >> ((i & 1) * 16)) & 0xFFFFu;
        float d = rsqrtf(1.0f + (float)cnt);   // +1 = self-loop
        g_dinv[i] = d;
        float p = d * x[i];
        g_p[i] = __float2half(p);
        g_t[i] = p;  // self-loop term (full precision)
    }
}

__global__ void k_node2(const float* __restrict__ W1, const float* __restrict__ b1,
                        const float* __restrict__ W2, int n) {
    int i = blockIdx.x * blockDim.x + threadIdx.x;
    if (i < n) {
        float dv = g_dinv[i];
        float s = dv * g_t[i];  // layer-1 aggregated scalar
        float g0 = 0.0f, g1 = 0.0f;
        #pragma unroll
        for (int j = 0; j < 16; j++) {
            float h = fmaxf(fmaf(s, __ldg(&W1[j]), __ldg(&b1[j])), 0.0f);
            g0 = fmaf(h, __ldg(&W2[2 * j + 0]), g0);
            g1 = fmaf(h, __ldg(&W2[2 * j + 1]), g1);
        }
        float2 r = make_float2(dv * g0, dv * g1);
        g_rh[i] = __float22half2_rn(r);
        g_acc[i] = r;  // self-loop term stays fp32
    }
}

__global__ void k_out(const float* __restrict__ b2, float* __restrict__ out, int n) {
    int i = blockIdx.x * blockDim.x + threadIdx.x;
    if (i < n) {
        float dv = g_dinv[i];
        float2 a = g_acc[i];
        float z0 = fmaf(dv, a.x, __ldg(&b2[0]));
        float z1 = fmaf(dv, a.y, __ldg(&b2[1]));
        float m = fmaxf(z0, z1);
        float lse = m + logf(expf(z0 - m) + expf(z1 - m));
        out[2 * i + 0] = z0 - lse;
        out[2 * i + 1] = z1 - lse;
    }
}

// -------- degree: smem-privatized packed histogram (off the L1tex path) ----

__global__ void k_deg(const int* __restrict__ dst, int E) {
    extern __shared__ uint32_t hist[];  // HWORDS words = 200KB
    for (int i = threadIdx.x; i < HWORDS; i += blockDim.x) hist[i] = 0u;
    __syncthreads();

    int e8 = E >> 3;
    int stride = gridDim.x * blockDim.x;
    for (int i = blockIdx.x * blockDim.x + threadIdx.x; i < e8; i += stride) {
        int4 a = __ldcg(reinterpret_cast<const int4*>(dst) + 2 * i);
        int4 b = __ldcg(reinterpret_cast<const int4*>(dst) + 2 * i + 1);
        atomicAdd(&hist[a.x >> 1], 1u << ((a.x & 1) * 16));
        atomicAdd(&hist[a.y >> 1], 1u << ((a.y & 1) * 16));
        atomicAdd(&hist[a.z >> 1], 1u << ((a.z & 1) * 16));
        atomicAdd(&hist[a.w >> 1], 1u << ((a.w & 1) * 16));
        atomicAdd(&hist[b.x >> 1], 1u << ((b.x & 1) * 16));
        atomicAdd(&hist[b.y >> 1], 1u << ((b.y & 1) * 16));
        atomicAdd(&hist[b.z >> 1], 1u << ((b.z & 1) * 16));
        atomicAdd(&hist[b.w >> 1], 1u << ((b.w & 1) * 16));
    }
    if (blockIdx.x == 0) {  // tail
        for (int e = (e8 << 3) + (int)threadIdx.x; e < E; e += blockDim.x) {
            int d = dst[e];
            atomicAdd(&hist[d >> 1], 1u << ((d & 1) * 16));
        }
    }
    __syncthreads();

    for (int i = threadIdx.x; i < HWORDS; i += blockDim.x) {
        uint32_t v = hist[i];
        if (v) atomicAdd(&g_degpack[i], v);
    }
}

// ---------------- layer-1 aggregation: single pass ----------------

__global__ void k_agg1(const int* __restrict__ src, const int* __restrict__ dst, int E) {
    int i = blockIdx.x * blockDim.x + threadIdx.x;
    int base = i * 8;
    if (base + 7 < E) {
        int4 sa = __ldcg(reinterpret_cast<const int4*>(src) + 2 * i);
        int4 sb = __ldcg(reinterpret_cast<const int4*>(src) + 2 * i + 1);
        int4 da = __ldcg(reinterpret_cast<const int4*>(dst) + 2 * i);
        int4 db = __ldcg(reinterpret_cast<const int4*>(dst) + 2 * i + 1);
        red_add_f32(&g_t[da.x], __half2float(__ldg(&g_p[sa.x])));
        red_add_f32(&g_t[da.y], __half2float(__ldg(&g_p[sa.y])));
        red_add_f32(&g_t[da.z], __half2float(__ldg(&g_p[sa.z])));
        red_add_f32(&g_t[da.w], __half2float(__ldg(&g_p[sa.w])));
        red_add_f32(&g_t[db.x], __half2float(__ldg(&g_p[sb.x])));
        red_add_f32(&g_t[db.y], __half2float(__ldg(&g_p[sb.y])));
        red_add_f32(&g_t[db.z], __half2float(__ldg(&g_p[sb.z])));
        red_add_f32(&g_t[db.w], __half2float(__ldg(&g_p[sb.w])));
    } else if (base < E) {
        for (int e = base; e < E; ++e)
            red_add_f32(&g_t[dst[e]], __half2float(__ldg(&g_p[src[e]])));
    }
}

// ---------------- layer-2 aggregation: single pass ----------------

__device__ __forceinline__ void agg2_one(int s, int d) {
    float2 r = __half22float2(__ldg(&g_rh[s]));
    red_add_v2(&g_acc[d], r.x, r.y);
}

__global__ void k_agg2(const int* __restrict__ src, const int* __restrict__ dst, int E) {
    int i = blockIdx.x * blockDim.x + threadIdx.x;
    int base = i * 8;
    if (base + 7 < E) {
        int4 sa = __ldcg(reinterpret_cast<const int4*>(src) + 2 * i);
        int4 sb = __ldcg(reinterpret_cast<const int4*>(src) + 2 * i + 1);
        int4 da = __ldcg(reinterpret_cast<const int4*>(dst) + 2 * i);
        int4 db = __ldcg(reinterpret_cast<const int4*>(dst) + 2 * i + 1);
        agg2_one(sa.x, da.x);
        agg2_one(sa.y, da.y);
        agg2_one(sa.z, da.z);
        agg2_one(sa.w, da.w);
        agg2_one(sb.x, db.x);
        agg2_one(sb.y, db.y);
        agg2_one(sb.z, db.z);
        agg2_one(sb.w, db.w);
    } else if (base < E) {
        for (int e = base; e < E; ++e) agg2_one(src[e], dst[e]);
    }
}

// ---------------- launch ----------------

extern "C" void kernel_launch(void* const* d_in, const int* in_sizes, int n_in,
                              void* d_out, int out_size) {
    const float* x  = (const float*)d_in[0];
    const int*   ei = (const int*)  d_in[1];
    const float* W1 = (const float*)d_in[2];
    const float* b1 = (const float*)d_in[3];
    const float* W2 = (const float*)d_in[4];
    const float* b2 = (const float*)d_in[5];
    int n = in_sizes[0];        // x is [N, 1]
    int E = in_sizes[1] / 2;    // edge_index is [2, E]
    const int* src = ei;
    const int* dst = ei + E;

    const int HIST_BYTES = HWORDS * 4;  // 200 KB
    cudaFuncSetAttribute(k_deg, cudaFuncAttributeMaxDynamicSharedMemorySize, HIST_BYTES);

    const int TB = 256;
    int nb_n = (n + TB - 1) / TB;
    int nb_h = (HWORDS + TB - 1) / TB;
    int e8   = (E + 7) / 8;
    int nb_e = (e8 + TB - 1) / TB;

    k_init <<<nb_h, TB>>>();
    k_deg  <<<148, 1024, HIST_BYTES>>>(dst, E);
    k_node1<<<nb_n, TB>>>(x, n);
    k_agg1 <<<nb_e, TB>>>(src, dst, E);
    k_node2<<<nb_n, TB>>>(W1, b1, W2, n);
    k_agg2 <<<nb_e, TB>>>(src, dst, E);
    k_out  <<<nb_n, TB>>>(b2, (float*)d_out, n);
}